// round 1
// baseline (speedup 1.0000x reference)
#include <cuda_runtime.h>

// Problem constants
#define BATCH 8
#define LEN   512
#define DIN   256
#define DP    257          // DIN + 1 (bias-augmented)
#define ODIM  64
#define NBL   (BATCH*LEN)  // 4096

// Scratch: T[bl][o][i], i contiguous.  4096*64*257 floats = 269.5 MB (zero-init bss)
__device__ float g_T[(size_t)NBL * ODIM * DP];

// ---------------------------------------------------------------------------
// K1: T[bl,o,i] = sum_j U[o,i,j] * x1a[bl,j]
//   grid = (64 bl-tiles, 64 o) ; block = 256 threads
//   SMEM: x1s [256][65] k-major, Usm [64][65] k-major, Urow [257]
//   Bias column j=256 folded into acc init (x1a[bl,256] == 1).
//   Row i=256 computed in a small tail (T[bl,o,256] = sum_j U[o,256,j]*x1a[j]).
// ---------------------------------------------------------------------------
__global__ __launch_bounds__(256) void k1_kernel(const float* __restrict__ x1,
                                                 const float* __restrict__ U) {
    extern __shared__ float sm[];
    float* x1s  = sm;                 // [256][65]
    float* Usm  = sm + 256 * 65;      // [64][65]
    float* Urow = Usm + 64 * 65;      // [257]

    const int blbase = blockIdx.x * 64;
    const int o      = blockIdx.y;
    const int tid    = threadIdx.x;
    const int tn     = tid & 15;      // -> i
    const int tm     = tid >> 4;      // -> bl

    // Load x1 tile (64 bl x 256 j), store k(j)-major with pad-65 (conflict-free)
    for (int e = tid; e < 64 * 256; e += 256) {
        int bl = e >> 8, j = e & 255;
        x1s[j * 65 + bl] = x1[(size_t)(blbase + bl) * 256 + j];
    }
    // U[o][256][j] row for the i=256 tail
    for (int e = tid; e < 257; e += 256)
        Urow[e] = U[((size_t)o * 257 + 256) * 257 + e];
    __syncthreads();

    for (int ic = 0; ic < 4; ic++) {
        const int i0 = ic * 64;

        // acc init = bias term: U[o, i, 256] * x1a[bl,256](=1)
        float binit[4];
        #pragma unroll
        for (int c = 0; c < 4; c++)
            binit[c] = U[((size_t)o * 257 + (i0 + tn * 4 + c)) * 257 + 256];
        float acc[4][4];
        #pragma unroll
        for (int r = 0; r < 4; r++)
            #pragma unroll
            for (int c = 0; c < 4; c++) acc[r][c] = binit[c];

        for (int jc = 0; jc < 4; jc++) {
            const int j0 = jc * 64;
            __syncthreads();   // previous Usm readers done
            for (int e = tid; e < 64 * 64; e += 256) {
                int ii = e >> 6, jj = e & 63;
                Usm[jj * 65 + ii] = U[((size_t)o * 257 + (i0 + ii)) * 257 + (j0 + jj)];
            }
            __syncthreads();

            #pragma unroll 8
            for (int kk = 0; kk < 64; kk++) {
                float a[4], bb[4];
                #pragma unroll
                for (int r = 0; r < 4; r++) a[r]  = x1s[(j0 + kk) * 65 + tm * 4 + r];
                #pragma unroll
                for (int c = 0; c < 4; c++) bb[c] = Usm[kk * 65 + tn * 4 + c];
                #pragma unroll
                for (int r = 0; r < 4; r++)
                    #pragma unroll
                    for (int c = 0; c < 4; c++)
                        acc[r][c] = fmaf(a[r], bb[c], acc[r][c]);
            }
        }

        // store T tile (i contiguous, coalesced)
        #pragma unroll
        for (int r = 0; r < 4; r++) {
            int bl = blbase + tm * 4 + r;
            size_t base = ((size_t)bl * ODIM + o) * DP + i0 + tn * 4;
            #pragma unroll
            for (int c = 0; c < 4; c++) g_T[base + c] = acc[r][c];
        }
    }

    // Tail: i = 256 (x1s and Urow are never overwritten; no extra sync needed)
    if (tid < 64) {
        int bl = tid;
        float s = Urow[256];   // U[o,256,256] * 1
        #pragma unroll 8
        for (int j = 0; j < 256; j++)
            s = fmaf(x1s[j * 65 + bl], Urow[j], s);
        g_T[((size_t)(blbase + bl) * ODIM + o) * DP + 256] = s;
    }
}

// ---------------------------------------------------------------------------
// K2: out[bl,m,o] = sum_i T[bl,o,i] * x2a[b,m,i]
//   grid = 4096 (one CTA per bl) ; block = 256 threads
//   SMEM: Ts [257][65] k(i)-major, x2s [256][65] k(i)-major
//   Bias term i=256 (x2a[m,256]==1) folded into acc init = Ts[256][o].
// ---------------------------------------------------------------------------
__global__ __launch_bounds__(256) void k2_kernel(const float* __restrict__ x2,
                                                 float* __restrict__ out) {
    extern __shared__ float sm[];
    float* Ts  = sm;               // [257][65]
    float* x2s = sm + 257 * 65;    // [256][65]

    const int bl  = blockIdx.x;
    const int b   = bl >> 9;
    const int tid = threadIdx.x;
    const int tn  = tid & 15;      // -> o
    const int tm  = tid >> 4;      // -> m

    // Load T[bl] (64 o x 257 i), store i-major with pad-65
    for (int e = tid; e < ODIM * DP; e += 256) {
        int oo = e / DP;
        int i  = e - oo * DP;
        Ts[i * 65 + oo] = g_T[((size_t)bl * ODIM + oo) * DP + i];
    }
    __syncthreads();

    float binit[4];
    #pragma unroll
    for (int c = 0; c < 4; c++) binit[c] = Ts[256 * 65 + tn * 4 + c];

    for (int mc = 0; mc < 8; mc++) {
        const int m0 = mc * 64;
        __syncthreads();   // previous x2s readers done
        for (int e = tid; e < 64 * 256; e += 256) {
            int mm = e >> 8, i = e & 255;
            x2s[i * 65 + mm] = x2[((size_t)b * LEN + m0 + mm) * 256 + i];
        }
        __syncthreads();

        float acc[4][4];
        #pragma unroll
        for (int r = 0; r < 4; r++)
            #pragma unroll
            for (int c = 0; c < 4; c++) acc[r][c] = binit[c];

        #pragma unroll 8
        for (int kk = 0; kk < 256; kk++) {
            float a[4], bb[4];
            #pragma unroll
            for (int r = 0; r < 4; r++) a[r]  = x2s[kk * 65 + tm * 4 + r];
            #pragma unroll
            for (int c = 0; c < 4; c++) bb[c] = Ts[kk * 65 + tn * 4 + c];
            #pragma unroll
            for (int r = 0; r < 4; r++)
                #pragma unroll
                for (int c = 0; c < 4; c++)
                    acc[r][c] = fmaf(a[r], bb[c], acc[r][c]);
        }

        // out[(bl*512 + m)*64 + o], o contiguous -> coalesced 256B rows
        #pragma unroll
        for (int r = 0; r < 4; r++) {
            int m = m0 + tm * 4 + r;
            size_t base = ((size_t)bl * LEN + m) * ODIM + tn * 4;
            #pragma unroll
            for (int c = 0; c < 4; c++) out[base + c] = acc[r][c];
        }
    }
}

// ---------------------------------------------------------------------------
extern "C" void kernel_launch(void* const* d_in, const int* in_sizes, int n_in,
                              void* d_out, int out_size) {
    const float* x1 = (const float*)d_in[0];   // (8,512,1,256)
    const float* x2 = (const float*)d_in[1];   // (8,1,512,256)
    const float* U  = (const float*)d_in[2];   // (64,257,257)
    float* out = (float*)d_out;                // (8,512,512,64) fp32

    const size_t SM1 = (size_t)(256 * 65 + 64 * 65 + 257) * sizeof(float);  // ~84.2 KB
    const size_t SM2 = (size_t)(257 * 65 + 256 * 65) * sizeof(float);       // ~133.4 KB

    cudaFuncSetAttribute(k1_kernel, cudaFuncAttributeMaxDynamicSharedMemorySize, (int)SM1);
    cudaFuncSetAttribute(k2_kernel, cudaFuncAttributeMaxDynamicSharedMemorySize, (int)SM2);

    k1_kernel<<<dim3(64, 64), 256, SM1>>>(x1, U);
    k2_kernel<<<NBL, 256, SM2>>>(x2, out);
}

// round 5
// speedup vs baseline: 3.3865x; 3.3865x over previous
#include <cuda_runtime.h>
#include <cuda_bf16.h>
#include <cstdint>

#define NBL 4096          // B*L
#define DK  256           // MMA-covered K extent (index 256 handled exactly in fp32)
#define OD  64

// ---------------- device scratch (no allocs allowed) ----------------
__device__ __align__(16) __nv_bfloat16 g_x1h[NBL*DK], g_x1l[NBL*DK];
__device__ __align__(16) __nv_bfloat16 g_x2h[NBL*DK], g_x2l[NBL*DK];
__device__ __align__(16) __nv_bfloat16 g_Uh[(size_t)OD*DK*DK], g_Ul[(size_t)OD*DK*DK];
__device__ __align__(16) __nv_bfloat16 g_Th[(size_t)NBL*OD*DK], g_Tl[(size_t)NBL*OD*DK];
__device__ float g_t256[NBL*OD];

// ---------------- helpers (baseline sm_90 ISA only: no tcgen05) ----------------
__device__ __forceinline__ uint32_t s2u(const void* p) {
    uint32_t a;
    asm("{ .reg .u64 t; cvta.to.shared.u64 t, %1; cvt.u32.u64 %0, t; }" : "=r"(a) : "l"(p));
    return a;
}
__device__ __forceinline__ void cp16(uint32_t s, const void* g) {
    asm volatile("cp.async.cg.shared.global [%0], [%1], 16;" :: "r"(s), "l"(g));
}
__device__ __forceinline__ void cp_commit() {
    asm volatile("cp.async.commit_group;");
}
template<int N> __device__ __forceinline__ void cp_wait() {
    asm volatile("cp.async.wait_group %0;" :: "n"(N));
}
__device__ __forceinline__ void ldsm4(uint32_t r[4], uint32_t addr) {
    asm volatile("ldmatrix.sync.aligned.m8n8.x4.shared.b16 {%0,%1,%2,%3}, [%4];"
        : "=r"(r[0]), "=r"(r[1]), "=r"(r[2]), "=r"(r[3]) : "r"(addr));
}
__device__ __forceinline__ void mma16(float c[4], const uint32_t a[4], uint32_t b0, uint32_t b1) {
    asm volatile("mma.sync.aligned.m16n8k16.row.col.f32.bf16.bf16.f32 "
        "{%0,%1,%2,%3}, {%4,%5,%6,%7}, {%8,%9}, {%0,%1,%2,%3};"
        : "+f"(c[0]), "+f"(c[1]), "+f"(c[2]), "+f"(c[3])
        : "r"(a[0]), "r"(a[1]), "r"(a[2]), "r"(a[3]), "r"(b0), "r"(b1));
}

// SMEM chunk buffer layout (bytes), rows padded to 80B (k=32 bf16 = 64B + 16B pad)
// -> ldmatrix groups of 8 consecutive rows hit banks r*20%32 = all distinct.
#define AHOFF 0
#define ALOFF 10240u   // 128 rows * 80B
#define BHOFF 20480u
#define BLOFF 25600u   // + 64 rows * 80B
#define BUFSZ 30720u
#define SMEMB (256u + 2u*BUFSZ)   // 61,696 B -> 3 CTAs/SM

__device__ __forceinline__ void copy_chunk(uint32_t bufb,
        const __nv_bfloat16* Ah, const __nv_bfloat16* Al,
        const __nv_bfloat16* Bh, const __nv_bfloat16* Bl, int k0) {
    const int tid = threadIdx.x;
    #pragma unroll
    for (int u = tid; u < 512; u += 256) {            // A: 128 rows x 4 16B-units
        int row = u >> 2, c = u & 3;
        uint32_t d = bufb + row * 80 + c * 16;
        const size_t go = (size_t)row * DK + k0 + c * 8;
        cp16(d + AHOFF, Ah + go);
        cp16(d + ALOFF, Al + go);
    }
    {                                                  // B: 64 rows x 4 units = 256
        int row = tid >> 2, c = tid & 3;
        uint32_t d = bufb + row * 80 + c * 16;
        const size_t go = (size_t)row * DK + k0 + c * 8;
        cp16(d + BHOFF, Bh + go);
        cp16(d + BLOFF, Bl + go);
    }
    cp_commit();
}

__device__ __forceinline__ void compute_chunk(uint32_t bufb, int lane, int wm, int wn,
                                              float c[2][4][4]) {
    // ldmatrix base addrs: row = tile_row + (lane&15), 16B-group = lane>>4
    uint32_t rowA = bufb + AHOFF + (uint32_t)((wm * 32 + (lane & 15)) * 80 + ((lane >> 4) * 16));
    uint32_t rowB = bufb + BHOFF + (uint32_t)((wn * 32 + (lane & 15)) * 80 + ((lane >> 4) * 16));
    #pragma unroll
    for (int ks = 0; ks < 2; ks++) {
        uint32_t aH[2][4], aL[2][4], bH[2][4], bL[2][4];
        #pragma unroll
        for (int t = 0; t < 2; t++) {
            ldsm4(aH[t], rowA + t * 1280 + ks * 32);                  // 16 rows * 80B = 1280
            ldsm4(aL[t], rowA + (ALOFF - AHOFF) + t * 1280 + ks * 32);
        }
        #pragma unroll
        for (int g = 0; g < 2; g++) {
            ldsm4(bH[g], rowB + g * 1280 + ks * 32);
            ldsm4(bL[g], rowB + (BLOFF - BHOFF) + g * 1280 + ks * 32);
        }
        #pragma unroll
        for (int t = 0; t < 2; t++)
            #pragma unroll
            for (int g = 0; g < 2; g++)
                #pragma unroll
                for (int h = 0; h < 2; h++) {
                    float* acc = c[t][g * 2 + h];
                    mma16(acc, aH[t], bH[g][h], bH[g][h + 2]);   // hi*hi
                    mma16(acc, aH[t], bL[g][h], bL[g][h + 2]);   // hi*lo
                    mma16(acc, aL[t], bH[g][h], bH[g][h + 2]);   // lo*hi
                }
    }
}

__device__ __forceinline__ void run_gemm(uint32_t sb,
        const __nv_bfloat16* Ah, const __nv_bfloat16* Al,
        const __nv_bfloat16* Bh, const __nv_bfloat16* Bl,
        int lane, int wm, int wn, float c[2][4][4]) {
    #pragma unroll
    for (int t = 0; t < 2; t++)
        #pragma unroll
        for (int n = 0; n < 4; n++)
            #pragma unroll
            for (int e = 0; e < 4; e++) c[t][n][e] = 0.f;

    const uint32_t b0 = sb + 256, b1 = b0 + BUFSZ;
    copy_chunk(b0, Ah, Al, Bh, Bl, 0);
    #pragma unroll 1
    for (int kc = 0; kc < 8; kc++) {
        if (kc < 7) {
            copy_chunk(((kc + 1) & 1) ? b1 : b0, Ah, Al, Bh, Bl, (kc + 1) * 32);
            cp_wait<1>();
        } else {
            cp_wait<0>();
        }
        __syncthreads();
        compute_chunk((kc & 1) ? b1 : b0, lane, wm, wn, c);
        __syncthreads();
    }
}

// ---------------- preprocessing ----------------
__global__ __launch_bounds__(256) void x1split(const float* __restrict__ s) {
    int i = blockIdx.x * 256 + threadIdx.x;
    float x = s[i];
    __nv_bfloat16 h = __float2bfloat16(x);
    g_x1h[i] = h; g_x1l[i] = __float2bfloat16(x - __bfloat162float(h));
}
__global__ __launch_bounds__(256) void x2split(const float* __restrict__ s) {
    int i = blockIdx.x * 256 + threadIdx.x;
    float x = s[i];
    __nv_bfloat16 h = __float2bfloat16(x);
    g_x2h[i] = h; g_x2l[i] = __float2bfloat16(x - __bfloat162float(h));
}
__global__ __launch_bounds__(256) void usplit(const float* __restrict__ U) {
    size_t idx = (size_t)blockIdx.x * 256 + threadIdx.x;   // 64*256*256
    int o = (int)(idx >> 16), r = (int)(idx & 65535), i = r >> 8, j = r & 255;
    float x = U[((size_t)o * 257 + i) * 257 + j];
    __nv_bfloat16 h = __float2bfloat16(x);
    g_Uh[idx] = h; g_Ul[idx] = __float2bfloat16(x - __bfloat162float(h));
}
// t256[bl,o] = sum_j U[o,256,j]*x1a[bl,j] + U[o,256,256]  (exact fp32)
__global__ __launch_bounds__(256) void t256_k(const float* __restrict__ x1,
                                              const float* __restrict__ U) {
    extern __shared__ float x1s[];   // 64 x 256
    int bl0 = blockIdx.x * 64, tid = threadIdx.x;
    for (int e = tid; e < 64 * 256; e += 256)
        x1s[e] = x1[(size_t)(bl0 + (e >> 8)) * 256 + (e & 255)];
    __syncthreads();
    for (int idx = tid; idx < 4096; idx += 256) {
        int o = idx & 63, bl = idx >> 6;
        const float* ur = U + ((size_t)o * 257 + 256) * 257;
        float acc = ur[256];
        #pragma unroll 8
        for (int j = 0; j < 256; j++) acc = fmaf(x1s[bl * 256 + j], ur[j], acc);
        g_t256[(size_t)(bl0 + bl) * 64 + o] = acc;
    }
}

// ---------------- K1: T[bl,o,i] = sum_j U[o,i,j]*x1a[bl,j] ----------------
__global__ __launch_bounds__(256, 3) void k1_mm(const float* __restrict__ U) {
    extern __shared__ char sm[];
    uint32_t sb = s2u(sm);
    const int tid = threadIdx.x, lane = tid & 31, wid = tid >> 5;
    const int wm = wid >> 1, wn = wid & 1;
    const int bl0 = blockIdx.x * 128, o = blockIdx.y, i0 = blockIdx.z * 64;

    float* ub = (float*)sm;   // bias col U[o, i0+n, 256]
    if (tid < 64) ub[tid] = U[((size_t)o * 257 + i0 + tid) * 257 + 256];

    float c[2][4][4];
    run_gemm(sb,
             g_x1h + (size_t)bl0 * DK, g_x1l + (size_t)bl0 * DK,
             g_Uh + (size_t)o * DK * DK + (size_t)i0 * DK,
             g_Ul + (size_t)o * DK * DK + (size_t)i0 * DK,
             lane, wm, wn, c);

    const int mr = wm * 32 + (lane >> 2);
    const int nc = wn * 32 + (lane & 3) * 2;
    #pragma unroll
    for (int t = 0; t < 2; t++)
        #pragma unroll
        for (int n8 = 0; n8 < 4; n8++) {
            int n = nc + n8 * 8;
            float b0f = ub[n], b1f = ub[n + 1];
            #pragma unroll
            for (int h = 0; h < 2; h++) {
                int m = bl0 + mr + t * 16 + h * 8;
                float v0 = c[t][n8][h * 2 + 0] + b0f;
                float v1 = c[t][n8][h * 2 + 1] + b1f;
                __nv_bfloat16 h0 = __float2bfloat16(v0);
                __nv_bfloat16 h1 = __float2bfloat16(v1);
                __nv_bfloat162 ph; ph.x = h0; ph.y = h1;
                __nv_bfloat162 pl;
                pl.x = __float2bfloat16(v0 - __bfloat162float(h0));
                pl.y = __float2bfloat16(v1 - __bfloat162float(h1));
                size_t base = ((size_t)m * OD + o) * DK + i0 + n;
                *reinterpret_cast<__nv_bfloat162*>(g_Th + base) = ph;
                *reinterpret_cast<__nv_bfloat162*>(g_Tl + base) = pl;
            }
        }
}

// ---------------- K2: out[bl,m,o] = sum_i x2a[m,i]*T[bl,o,i] ----------------
__global__ __launch_bounds__(256, 3) void k2_mm(float* __restrict__ out) {
    extern __shared__ char sm[];
    uint32_t sb = s2u(sm);
    const int tid = threadIdx.x, lane = tid & 31, wid = tid >> 5;
    const int wm = wid >> 1, wn = wid & 1;
    const int bl = blockIdx.x, mb = blockIdx.y, b = bl >> 9;

    float* t2 = (float*)sm;   // T[bl,o,256] broadcast (x2a[m,256]==1)
    if (tid < 64) t2[tid] = g_t256[(size_t)bl * OD + tid];

    float c[2][4][4];
    run_gemm(sb,
             g_x2h + (size_t)(b * 512 + mb * 128) * DK,
             g_x2l + (size_t)(b * 512 + mb * 128) * DK,
             g_Th + (size_t)bl * OD * DK, g_Tl + (size_t)bl * OD * DK,
             lane, wm, wn, c);

    const int mr = wm * 32 + (lane >> 2);
    const int nc = wn * 32 + (lane & 3) * 2;
    #pragma unroll
    for (int t = 0; t < 2; t++)
        #pragma unroll
        for (int n8 = 0; n8 < 4; n8++) {
            int n = nc + n8 * 8;
            float b0f = t2[n], b1f = t2[n + 1];
            #pragma unroll
            for (int h = 0; h < 2; h++) {
                int m = mb * 128 + mr + t * 16 + h * 8;
                float2 v;
                v.x = c[t][n8][h * 2 + 0] + b0f;
                v.y = c[t][n8][h * 2 + 1] + b1f;
                *reinterpret_cast<float2*>(out + ((size_t)bl * 512 + m) * OD + n) = v;
            }
        }
}

// ---------------- launch ----------------
extern "C" void kernel_launch(void* const* d_in, const int* in_sizes, int n_in,
                              void* d_out, int out_size) {
    const float* x1 = (const float*)d_in[0];   // (8,512,1,256)
    const float* x2 = (const float*)d_in[1];   // (8,1,512,256)
    const float* U  = (const float*)d_in[2];   // (64,257,257)
    float* out = (float*)d_out;                // (8,512,512,64)

    cudaFuncSetAttribute(t256_k, cudaFuncAttributeMaxDynamicSharedMemorySize, 65536);
    cudaFuncSetAttribute(k1_mm, cudaFuncAttributeMaxDynamicSharedMemorySize, (int)SMEMB);
    cudaFuncSetAttribute(k2_mm, cudaFuncAttributeMaxDynamicSharedMemorySize, (int)SMEMB);

    x1split<<<4096, 256>>>(x1);
    x2split<<<4096, 256>>>(x2);
    usplit<<<16384, 256>>>(U);
    t256_k<<<64, 256, 65536>>>(x1, U);
    k1_mm<<<dim3(32, 64, 4), 256, SMEMB>>>(U);
    k2_mm<<<dim3(4096, 4), 256, SMEMB>>>(out);
}

// round 8
// speedup vs baseline: 3.9440x; 1.1646x over previous
#include <cuda_runtime.h>
#include <cuda_bf16.h>
#include <cstdint>

#define NBL 4096          // B*L
#define DK  256           // MMA-covered K extent (index 256 handled exactly in fp32)
#define OD  64

// ---------------- device scratch (no allocs allowed) ----------------
__device__ __align__(16) __nv_bfloat16 g_x1h[NBL*DK], g_x1l[NBL*DK];
__device__ __align__(16) __nv_bfloat16 g_x2h[NBL*DK], g_x2l[NBL*DK];
__device__ __align__(16) __nv_bfloat16 g_Uh[(size_t)OD*DK*DK], g_Ul[(size_t)OD*DK*DK];
__device__ __align__(16) __nv_bfloat16 g_Th[(size_t)NBL*OD*DK], g_Tl[(size_t)NBL*OD*DK];
__device__ float g_t256[NBL*OD];

// ---------------- helpers (baseline sm_90 ISA only: no tcgen05) ----------------
__device__ __forceinline__ uint32_t s2u(const void* p) {
    uint32_t a;
    asm("{ .reg .u64 t; cvta.to.shared.u64 t, %1; cvt.u32.u64 %0, t; }" : "=r"(a) : "l"(p));
    return a;
}
__device__ __forceinline__ void cp16(uint32_t s, const void* g) {
    asm volatile("cp.async.cg.shared.global [%0], [%1], 16;" :: "r"(s), "l"(g));
}
__device__ __forceinline__ void cp_commit() {
    asm volatile("cp.async.commit_group;");
}
template<int N> __device__ __forceinline__ void cp_wait() {
    asm volatile("cp.async.wait_group %0;" :: "n"(N));
}
__device__ __forceinline__ void ldsm4(uint32_t r[4], uint32_t addr) {
    asm volatile("ldmatrix.sync.aligned.m8n8.x4.shared.b16 {%0,%1,%2,%3}, [%4];"
        : "=r"(r[0]), "=r"(r[1]), "=r"(r[2]), "=r"(r[3]) : "r"(addr));
}
__device__ __forceinline__ void mma16(float c[4], const uint32_t a[4], uint32_t b0, uint32_t b1) {
    asm volatile("mma.sync.aligned.m16n8k16.row.col.f32.bf16.bf16.f32 "
        "{%0,%1,%2,%3}, {%4,%5,%6,%7}, {%8,%9}, {%0,%1,%2,%3};"
        : "+f"(c[0]), "+f"(c[1]), "+f"(c[2]), "+f"(c[3])
        : "r"(a[0]), "r"(a[1]), "r"(a[2]), "r"(a[3]), "r"(b0), "r"(b1));
}

// ================= K1 (unchanged skeleton): per-chunk A+B buffers =================
// rows padded to 80B (k=32 bf16 = 64B + 16B pad) -> conflict-free ldmatrix
#define AHOFF 0
#define ALOFF 10240u   // 128 rows * 80B
#define BHOFF 20480u
#define BLOFF 25600u   // + 64 rows * 80B
#define BUFSZ 30720u
#define SMEMB (256u + 2u*BUFSZ)   // 61,696 B -> 3 CTAs/SM

__device__ __forceinline__ void copy_chunk(uint32_t bufb,
        const __nv_bfloat16* Ah, const __nv_bfloat16* Al,
        const __nv_bfloat16* Bh, const __nv_bfloat16* Bl, int k0) {
    const int tid = threadIdx.x;
    #pragma unroll
    for (int u = tid; u < 512; u += 256) {            // A: 128 rows x 4 16B-units
        int row = u >> 2, c = u & 3;
        uint32_t d = bufb + row * 80 + c * 16;
        const size_t go = (size_t)row * DK + k0 + c * 8;
        cp16(d + AHOFF, Ah + go);
        cp16(d + ALOFF, Al + go);
    }
    {                                                  // B: 64 rows x 4 units = 256
        int row = tid >> 2, c = tid & 3;
        uint32_t d = bufb + row * 80 + c * 16;
        const size_t go = (size_t)row * DK + k0 + c * 8;
        cp16(d + BHOFF, Bh + go);
        cp16(d + BLOFF, Bl + go);
    }
    cp_commit();
}

__device__ __forceinline__ void compute_chunk(uint32_t bufb, int lane, int wm, int wn,
                                              float c[2][4][4]) {
    uint32_t rowA = bufb + AHOFF + (uint32_t)((wm * 32 + (lane & 15)) * 80 + ((lane >> 4) * 16));
    uint32_t rowB = bufb + BHOFF + (uint32_t)((wn * 32 + (lane & 15)) * 80 + ((lane >> 4) * 16));
    #pragma unroll
    for (int ks = 0; ks < 2; ks++) {
        uint32_t aH[2][4], aL[2][4], bH[2][4], bL[2][4];
        #pragma unroll
        for (int t = 0; t < 2; t++) {
            ldsm4(aH[t], rowA + t * 1280 + ks * 32);
            ldsm4(aL[t], rowA + (ALOFF - AHOFF) + t * 1280 + ks * 32);
        }
        #pragma unroll
        for (int g = 0; g < 2; g++) {
            ldsm4(bH[g], rowB + g * 1280 + ks * 32);
            ldsm4(bL[g], rowB + (BLOFF - BHOFF) + g * 1280 + ks * 32);
        }
        #pragma unroll
        for (int t = 0; t < 2; t++)
            #pragma unroll
            for (int g = 0; g < 2; g++)
                #pragma unroll
                for (int h = 0; h < 2; h++) {
                    float* acc = c[t][g * 2 + h];
                    mma16(acc, aH[t], bH[g][h], bH[g][h + 2]);   // hi*hi
                    mma16(acc, aH[t], bL[g][h], bL[g][h + 2]);   // hi*lo
                    mma16(acc, aL[t], bH[g][h], bH[g][h + 2]);   // lo*hi
                }
    }
}

__device__ __forceinline__ void run_gemm(uint32_t sb,
        const __nv_bfloat16* Ah, const __nv_bfloat16* Al,
        const __nv_bfloat16* Bh, const __nv_bfloat16* Bl,
        int lane, int wm, int wn, float c[2][4][4]) {
    #pragma unroll
    for (int t = 0; t < 2; t++)
        #pragma unroll
        for (int n = 0; n < 4; n++)
            #pragma unroll
            for (int e = 0; e < 4; e++) c[t][n][e] = 0.f;

    const uint32_t b0 = sb + 256, b1 = b0 + BUFSZ;
    copy_chunk(b0, Ah, Al, Bh, Bl, 0);
    #pragma unroll 1
    for (int kc = 0; kc < 8; kc++) {
        if (kc < 7) {
            copy_chunk(((kc + 1) & 1) ? b1 : b0, Ah, Al, Bh, Bl, (kc + 1) * 32);
            cp_wait<1>();
        } else {
            cp_wait<0>();
        }
        __syncthreads();
        compute_chunk((kc & 1) ? b1 : b0, lane, wm, wn, c);
        __syncthreads();
    }
}

// ---------------- preprocessing ----------------
__global__ __launch_bounds__(256) void x1split(const float* __restrict__ s) {
    int i = blockIdx.x * 256 + threadIdx.x;
    float x = s[i];
    __nv_bfloat16 h = __float2bfloat16(x);
    g_x1h[i] = h; g_x1l[i] = __float2bfloat16(x - __bfloat162float(h));
}
__global__ __launch_bounds__(256) void x2split(const float* __restrict__ s) {
    int i = blockIdx.x * 256 + threadIdx.x;
    float x = s[i];
    __nv_bfloat16 h = __float2bfloat16(x);
    g_x2h[i] = h; g_x2l[i] = __float2bfloat16(x - __bfloat162float(h));
}
__global__ __launch_bounds__(256) void usplit(const float* __restrict__ U) {
    size_t idx = (size_t)blockIdx.x * 256 + threadIdx.x;   // 64*256*256
    int o = (int)(idx >> 16), r = (int)(idx & 65535), i = r >> 8, j = r & 255;
    float x = U[((size_t)o * 257 + i) * 257 + j];
    __nv_bfloat16 h = __float2bfloat16(x);
    g_Uh[idx] = h; g_Ul[idx] = __float2bfloat16(x - __bfloat162float(h));
}

// t256[bl,o] = sum_j U[o,256,j]*x1a[bl,j] + U[o,256,256]  (exact fp32)
// 1024 CTAs: 4 bl x 64 o per CTA, one output/thread, all-smem inner loop.
// Us row stride 261 words (261 % 32 = 5, gcd(5,32)=1 -> conflict-free across o lanes).
__global__ __launch_bounds__(256) void t256_k(const float* __restrict__ x1,
                                              const float* __restrict__ U) {
    extern __shared__ char sm[];
    float* Us  = (float*)sm;             // 64 x 261
    float* x1s = (float*)sm + 64 * 261;  // 4 x 256
    const int bl0 = blockIdx.x * 4, tid = threadIdx.x;

    for (int e = tid; e < 64 * 257; e += 256) {
        int o = e / 257, j = e - o * 257;
        Us[o * 261 + j] = U[((size_t)o * 257 + 256) * 257 + j];
    }
    for (int e = tid; e < 4 * 256; e += 256)
        x1s[e] = x1[(size_t)(bl0 + (e >> 8)) * 256 + (e & 255)];
    __syncthreads();

    const int blq = tid >> 6, o = tid & 63;
    const float* ur = Us + o * 261;
    const float* xr = x1s + blq * 256;
    float p[8];
    #pragma unroll
    for (int u = 0; u < 8; u++) p[u] = 0.f;
    #pragma unroll 4
    for (int j = 0; j < 256; j += 8)
        #pragma unroll
        for (int u = 0; u < 8; u++) p[u] = fmaf(xr[j + u], ur[j + u], p[u]);
    float acc = ur[256];
    #pragma unroll
    for (int u = 0; u < 8; u++) acc += p[u];
    g_t256[(size_t)(bl0 + blq) * 64 + o] = acc;
}

// ---------------- K1: T[bl,o,i] = sum_j U[o,i,j]*x1a[bl,j] ----------------
__global__ __launch_bounds__(256, 3) void k1_mm(const float* __restrict__ U) {
    extern __shared__ char sm[];
    uint32_t sb = s2u(sm);
    const int tid = threadIdx.x, lane = tid & 31, wid = tid >> 5;
    const int wm = wid >> 1, wn = wid & 1;
    const int bl0 = blockIdx.x * 128, o = blockIdx.y, i0 = blockIdx.z * 64;

    float* ub = (float*)sm;   // bias col U[o, i0+n, 256]
    if (tid < 64) ub[tid] = U[((size_t)o * 257 + i0 + tid) * 257 + 256];

    float c[2][4][4];
    run_gemm(sb,
             g_x1h + (size_t)bl0 * DK, g_x1l + (size_t)bl0 * DK,
             g_Uh + (size_t)o * DK * DK + (size_t)i0 * DK,
             g_Ul + (size_t)o * DK * DK + (size_t)i0 * DK,
             lane, wm, wn, c);

    const int mr = wm * 32 + (lane >> 2);
    const int nc = wn * 32 + (lane & 3) * 2;
    #pragma unroll
    for (int t = 0; t < 2; t++)
        #pragma unroll
        for (int n8 = 0; n8 < 4; n8++) {
            int n = nc + n8 * 8;
            float b0f = ub[n], b1f = ub[n + 1];
            #pragma unroll
            for (int h = 0; h < 2; h++) {
                int m = bl0 + mr + t * 16 + h * 8;
                float v0 = c[t][n8][h * 2 + 0] + b0f;
                float v1 = c[t][n8][h * 2 + 1] + b1f;
                __nv_bfloat16 h0 = __float2bfloat16(v0);
                __nv_bfloat16 h1 = __float2bfloat16(v1);
                __nv_bfloat162 ph; ph.x = h0; ph.y = h1;
                __nv_bfloat162 pl;
                pl.x = __float2bfloat16(v0 - __bfloat162float(h0));
                pl.y = __float2bfloat16(v1 - __bfloat162float(h1));
                size_t base = ((size_t)m * OD + o) * DK + i0 + n;
                *reinterpret_cast<__nv_bfloat162*>(g_Th + base) = ph;
                *reinterpret_cast<__nv_bfloat162*>(g_Tl + base) = pl;
            }
        }
}

// ================= K2: persistent-B, one CTA per bl, internal m-loop =================
// smem: [0,256) t2 | BH 64x528B | BL | A double buffers (chunk layout, 80B rows)
#define K2_BH   256u
#define K2_BL   34048u     // 256 + 64*528
#define K2_A0   67840u     // 256 + 2*33792
#define K2_A1   88320u     // + 20480
#define K2_SMEM 108800u    // -> 2 CTAs/SM

__device__ __forceinline__ void copy_B_full(uint32_t bbase,
        const __nv_bfloat16* Bh, const __nv_bfloat16* Bl) {
    const int tid = threadIdx.x;
    #pragma unroll
    for (int u = tid; u < 2048; u += 256) {   // 64 rows x 32 16B-units
        int row = u >> 5, c = u & 31;
        uint32_t d = bbase + row * 528 + c * 16;
        size_t go = (size_t)row * DK + c * 8;
        cp16(d, Bh + go);
        cp16(d + 33792u, Bl + go);
    }
}
__device__ __forceinline__ void copy_A_chunk(uint32_t bufb,
        const __nv_bfloat16* Ah, const __nv_bfloat16* Al, int k0) {
    const int tid = threadIdx.x;
    #pragma unroll
    for (int u = tid; u < 512; u += 256) {    // 128 rows x 4 16B-units
        int row = u >> 2, c = u & 3;
        uint32_t d = bufb + row * 80 + c * 16;
        size_t go = (size_t)row * DK + k0 + c * 8;
        cp16(d, Ah + go);
        cp16(d + 10240u, Al + go);
    }
}
__device__ __forceinline__ void compute_chunk_k2(uint32_t ab, uint32_t bb, int koffB,
                                                 int lane, int wm, int wn, float c[2][4][4]) {
    uint32_t rowA = ab + (uint32_t)((wm * 32 + (lane & 15)) * 80 + ((lane >> 4) * 16));
    uint32_t rowB = bb + (uint32_t)((wn * 32 + (lane & 15)) * 528 + ((lane >> 4) * 16) + koffB);
    #pragma unroll
    for (int ks = 0; ks < 2; ks++) {
        uint32_t aH[2][4], aL[2][4], bH[2][4], bL[2][4];
        #pragma unroll
        for (int t = 0; t < 2; t++) {
            ldsm4(aH[t], rowA + t * 1280 + ks * 32);
            ldsm4(aL[t], rowA + 10240u + t * 1280 + ks * 32);
        }
        #pragma unroll
        for (int g = 0; g < 2; g++) {
            ldsm4(bH[g], rowB + g * 8448 + ks * 32);          // 16 rows * 528B
            ldsm4(bL[g], rowB + 33792u + g * 8448 + ks * 32);
        }
        #pragma unroll
        for (int t = 0; t < 2; t++)
            #pragma unroll
            for (int g = 0; g < 2; g++)
                #pragma unroll
                for (int h = 0; h < 2; h++) {
                    float* acc = c[t][g * 2 + h];
                    mma16(acc, aH[t], bH[g][h], bH[g][h + 2]);
                    mma16(acc, aH[t], bL[g][h], bL[g][h + 2]);
                    mma16(acc, aL[t], bH[g][h], bH[g][h + 2]);
                }
    }
}

__global__ __launch_bounds__(256, 2) void k2_mm(float* __restrict__ out) {
    extern __shared__ char sm[];
    uint32_t sb = s2u(sm);
    const int tid = threadIdx.x, lane = tid & 31, wid = tid >> 5;
    const int wm = wid >> 1, wn = wid & 1;
    const int bl = blockIdx.x, b = bl >> 9;

    float* t2 = (float*)sm;   // T[bl,o,256] broadcast (x2a[m,256]==1)
    if (tid < 64) t2[tid] = g_t256[(size_t)bl * OD + tid];

    const __nv_bfloat16* Ahb = g_x2h + (size_t)(b * 512) * DK;
    const __nv_bfloat16* Alb = g_x2l + (size_t)(b * 512) * DK;

    copy_B_full(sb + K2_BH, g_Th + (size_t)bl * OD * DK, g_Tl + (size_t)bl * OD * DK);
    cp_commit();
    copy_A_chunk(sb + K2_A0, Ahb, Alb, 0);
    cp_commit();

    const uint32_t abuf[2] = { sb + K2_A0, sb + K2_A1 };
    const int mr = wm * 32 + (lane >> 2);
    const int nc = wn * 32 + (lane & 3) * 2;

    #pragma unroll 1
    for (int mb = 0; mb < 4; mb++) {
        float c[2][4][4];
        #pragma unroll
        for (int t = 0; t < 2; t++)
            #pragma unroll
            for (int n = 0; n < 4; n++)
                #pragma unroll
                for (int e = 0; e < 4; e++) c[t][n][e] = 0.f;

        #pragma unroll 1
        for (int kc = 0; kc < 8; kc++) {
            int it = mb * 8 + kc;
            if (it < 31) {
                int nx = it + 1, mb2 = nx >> 3, kc2 = nx & 7;
                copy_A_chunk(abuf[nx & 1], Ahb + (size_t)mb2 * 128 * DK,
                             Alb + (size_t)mb2 * 128 * DK, kc2 * 32);
                cp_commit();
                cp_wait<1>();
            } else {
                cp_wait<0>();
            }
            __syncthreads();
            compute_chunk_k2(abuf[it & 1], sb + K2_BH, kc * 64, lane, wm, wn, c);
            __syncthreads();
        }

        #pragma unroll
        for (int t = 0; t < 2; t++)
            #pragma unroll
            for (int n8 = 0; n8 < 4; n8++) {
                int n = nc + n8 * 8;
                float b0f = t2[n], b1f = t2[n + 1];
                #pragma unroll
                for (int h = 0; h < 2; h++) {
                    int m = mb * 128 + mr + t * 16 + h * 8;
                    float2 v;
                    v.x = c[t][n8][h * 2 + 0] + b0f;
                    v.y = c[t][n8][h * 2 + 1] + b1f;
                    *reinterpret_cast<float2*>(out + ((size_t)bl * 512 + m) * OD + n) = v;
                }
            }
    }
}

// ---------------- launch ----------------
extern "C" void kernel_launch(void* const* d_in, const int* in_sizes, int n_in,
                              void* d_out, int out_size) {
    const float* x1 = (const float*)d_in[0];   // (8,512,1,256)
    const float* x2 = (const float*)d_in[1];   // (8,1,512,256)
    const float* U  = (const float*)d_in[2];   // (64,257,257)
    float* out = (float*)d_out;                // (8,512,512,64)

    cudaFuncSetAttribute(t256_k, cudaFuncAttributeMaxDynamicSharedMemorySize, 70912);
    cudaFuncSetAttribute(k1_mm, cudaFuncAttributeMaxDynamicSharedMemorySize, (int)SMEMB);
    cudaFuncSetAttribute(k2_mm, cudaFuncAttributeMaxDynamicSharedMemorySize, (int)K2_SMEM);

    x1split<<<4096, 256>>>(x1);
    x2split<<<4096, 256>>>(x2);
    usplit<<<16384, 256>>>(U);
    t256_k<<<1024, 256, 70912>>>(x1, U);
    k1_mm<<<dim3(32, 64, 4), 256, SMEMB>>>(U);
    k2_mm<<<4096, 256, K2_SMEM>>>(out);
}